// round 3
// baseline (speedup 1.0000x reference)
#include <cuda_runtime.h>

// Problem constants
#define B_   32
#define C_   256
#define H_   128
#define W_   128
#define R_   128
#define F_   256
#define HP   126
#define WP   126
#define WPAD 128   // z padded width so GEMM-3 N-tiles are one full row

// Scratch (allocation-free: __device__ globals)
__device__ float g_y[(size_t)B_ * R_ * H_ * W_];     // [b][r][h][w]  268 MB
__device__ float g_z[(size_t)B_ * R_ * HP * WPAD];   // [b][r][p][wpad] 264 MB

// ---- packed f32x2 helpers (sm_103a) -------------------------------------
__device__ __forceinline__ unsigned long long pack_dup(float a) {
    unsigned long long r;
    asm("mov.b64 %0, {%1, %1};" : "=l"(r) : "f"(a));
    return r;
}
__device__ __forceinline__ void ffma2(unsigned long long &d,
                                      unsigned long long a,
                                      unsigned long long b) {
    asm("fma.rn.f32x2 %0, %1, %2, %0;" : "+l"(d) : "l"(a), "l"(b));
}
__device__ __forceinline__ float2 unpack2(unsigned long long v) {
    float2 f;
    asm("mov.b64 {%0, %1}, %2;" : "=f"(f.x), "=f"(f.y) : "l"(v));
    return f;
}

// =========================================================================
// Kernel 1: channel mix   y[b,r,h,w] = sum_c f3[c,r] * x[b,c,h,w]
// GEMM per (b, h-row): M=128 (r), N=128 (w), K=256 (c)
// =========================================================================
__global__ __launch_bounds__(256)
void k1_channel_mix(const float* __restrict__ x, const float* __restrict__ f3) {
    __shared__ float As[2][16][128];   // [k][r]
    __shared__ float Bs[2][16][128];   // [k][w]

    const int b  = blockIdx.y;
    const int h  = blockIdx.x;
    const int tid = threadIdx.x;
    const int tx = tid & 15, ty = tid >> 4;
    const int lk = tid >> 5;            // 0..7
    const int lm = (tid * 4) & 127;     // 0,4,...,124

    const float* Ag = f3;                                           // [256][128]
    const float* Bg = x + ((size_t)b * C_) * (H_ * W_) + (size_t)h * W_;

    unsigned long long acc[8][4];
#pragma unroll
    for (int i = 0; i < 8; ++i)
#pragma unroll
        for (int j = 0; j < 4; ++j) acc[i][j] = 0ULL;

    // preload chunk 0
    {
        float4 a0 = *(const float4*)(Ag + (size_t)(lk)     * R_ + lm);
        float4 a1 = *(const float4*)(Ag + (size_t)(lk + 8) * R_ + lm);
        float4 b0 = *(const float4*)(Bg + (size_t)(lk)     * (H_ * W_) + lm);
        float4 b1 = *(const float4*)(Bg + (size_t)(lk + 8) * (H_ * W_) + lm);
        *(float4*)&As[0][lk][lm]     = a0;
        *(float4*)&As[0][lk + 8][lm] = a1;
        *(float4*)&Bs[0][lk][lm]     = b0;
        *(float4*)&Bs[0][lk + 8][lm] = b1;
    }
    __syncthreads();

    int cur = 0;
#pragma unroll 1
    for (int kc = 0; kc < 16; ++kc) {
        float4 na0, na1, nb0, nb1;
        const bool more = (kc + 1) < 16;
        if (more) {
            int k0 = (kc + 1) * 16;
            na0 = *(const float4*)(Ag + (size_t)(k0 + lk)     * R_ + lm);
            na1 = *(const float4*)(Ag + (size_t)(k0 + lk + 8) * R_ + lm);
            nb0 = *(const float4*)(Bg + (size_t)(k0 + lk)     * (H_ * W_) + lm);
            nb1 = *(const float4*)(Bg + (size_t)(k0 + lk + 8) * (H_ * W_) + lm);
        }
#pragma unroll
        for (int k = 0; k < 16; ++k) {
            float4 a0 = *(const float4*)&As[cur][k][ty * 4];
            float4 a1 = *(const float4*)&As[cur][k][64 + ty * 4];
            ulonglong2 b0 = *(const ulonglong2*)&Bs[cur][k][tx * 4];
            ulonglong2 b1 = *(const ulonglong2*)&Bs[cur][k][64 + tx * 4];
            unsigned long long ap[8];
            ap[0] = pack_dup(a0.x); ap[1] = pack_dup(a0.y);
            ap[2] = pack_dup(a0.z); ap[3] = pack_dup(a0.w);
            ap[4] = pack_dup(a1.x); ap[5] = pack_dup(a1.y);
            ap[6] = pack_dup(a1.z); ap[7] = pack_dup(a1.w);
#pragma unroll
            for (int i = 0; i < 8; ++i) {
                ffma2(acc[i][0], ap[i], b0.x);
                ffma2(acc[i][1], ap[i], b0.y);
                ffma2(acc[i][2], ap[i], b1.x);
                ffma2(acc[i][3], ap[i], b1.y);
            }
        }
        if (more) {
            int nxt = cur ^ 1;
            *(float4*)&As[nxt][lk][lm]     = na0;
            *(float4*)&As[nxt][lk + 8][lm] = na1;
            *(float4*)&Bs[nxt][lk][lm]     = nb0;
            *(float4*)&Bs[nxt][lk + 8][lm] = nb1;
            __syncthreads();
            cur = nxt;
        }
    }

    // store y[b][r][h][w]
    float* yb = g_y + (((size_t)b * R_) * H_ + h) * W_;
#pragma unroll
    for (int i = 0; i < 8; ++i) {
        int r = (i < 4) ? (ty * 4 + i) : (64 + ty * 4 + (i - 4));
        float* row = yb + (size_t)r * (H_ * W_);
        float2 c0 = unpack2(acc[i][0]), c1 = unpack2(acc[i][1]);
        float2 c2 = unpack2(acc[i][2]), c3 = unpack2(acc[i][3]);
        *(float4*)(row + tx * 4)      = make_float4(c0.x, c0.y, c1.x, c1.y);
        *(float4*)(row + 64 + tx * 4) = make_float4(c2.x, c2.y, c3.x, c3.y);
    }
}

// =========================================================================
// Kernel 2: separable depthwise  z[b,r,p,q] = sum_{a,c} y[b,r,p+a,q+c]*f1[a,r]*f2[c,r]
// 4 outputs/thread along q; pads q=126,127 with zeros.
// =========================================================================
__global__ __launch_bounds__(128)
void k2_depthwise(const float* __restrict__ f1, const float* __restrict__ f2) {
    const int tid  = threadIdx.x;      // 128
    const int qg   = tid & 31;         // 0..31
    const int psub = tid >> 5;         // 0..3
    const int p = blockIdx.x * 4 + psub;
    const int r = blockIdx.y;
    const int b = blockIdx.z;
    if (p >= HP) return;

    const float w0 = f2[r],       w1 = f2[128 + r], w2 = f2[256 + r];
    const float v0 = f1[r],       v1 = f1[128 + r], v2 = f1[256 + r];

    const float* yb = g_y + ((((size_t)b * R_) + r) * H_ + p) * W_;
    const int q0 = qg * 4;

    float z0 = 0.f, z1 = 0.f, z2 = 0.f, z3 = 0.f;
#pragma unroll
    for (int a = 0; a < 3; ++a) {
        const float* row = yb + a * W_ + q0;
        float4 t = *(const float4*)row;
        float t4 = 0.f, t5 = 0.f;
        if (q0 + 5 <= 127) {
            float2 u = *(const float2*)(row + 4);
            t4 = u.x; t5 = u.y;
        }
        const float va = (a == 0) ? v0 : ((a == 1) ? v1 : v2);
        float h0 = t.x * w0 + t.y * w1 + t.z * w2;
        float h1 = t.y * w0 + t.z * w1 + t.w * w2;
        float h2 = t.z * w0 + t.w * w1 + t4  * w2;
        float h3 = t.w * w0 + t4  * w1 + t5  * w2;
        z0 += va * h0; z1 += va * h1; z2 += va * h2; z3 += va * h3;
    }
    if (qg == 31) { z2 = 0.f; z3 = 0.f; }   // pad columns 126,127

    float* zp = g_z + ((((size_t)b * R_) + r) * HP + p) * WPAD + q0;
    *(float4*)zp = make_float4(z0, z1, z2, z3);
}

// =========================================================================
// Kernel 3: out[b,f,p,q] = sum_r f0[f,r] * z[b,r,p,q]
// GEMM per (b, m-tile, p-row): M=128 (f), N=128 (q padded), K=128 (r)
// =========================================================================
__global__ __launch_bounds__(256)
void k3_output_gemm(const float* __restrict__ f0, float* __restrict__ out) {
    __shared__ float As[2][16][128];   // [k][f]  (transposed f0)
    __shared__ float Bs[2][16][128];   // [k][q]

    const int b  = blockIdx.z;
    const int m0 = blockIdx.y * 128;
    const int p  = blockIdx.x;          // 0..125
    const int tid = threadIdx.x;
    const int tx = tid & 15, ty = tid >> 4;
    const int am = (tid * 4) >> 4;      // 0..63 (pass 2 adds 64)
    const int ak = (tid * 4) & 15;      // 0,4,8,12
    const int lk = tid >> 5;
    const int lm = (tid * 4) & 127;

    const float* Ag = f0 + (size_t)m0 * R_;                         // [128][128]
    const float* Bg = g_z + (size_t)b * R_ * HP * WPAD + (size_t)p * WPAD;
    const int bstride = HP * WPAD;      // 16128

    unsigned long long acc[8][4];
#pragma unroll
    for (int i = 0; i < 8; ++i)
#pragma unroll
        for (int j = 0; j < 4; ++j) acc[i][j] = 0ULL;

    // preload chunk 0
    {
        float4 v0 = *(const float4*)(Ag + (size_t)am * R_ + ak);
        float4 v1 = *(const float4*)(Ag + (size_t)(am + 64) * R_ + ak);
        As[0][ak + 0][am] = v0.x; As[0][ak + 1][am] = v0.y;
        As[0][ak + 2][am] = v0.z; As[0][ak + 3][am] = v0.w;
        As[0][ak + 0][am + 64] = v1.x; As[0][ak + 1][am + 64] = v1.y;
        As[0][ak + 2][am + 64] = v1.z; As[0][ak + 3][am + 64] = v1.w;
        float4 b0 = *(const float4*)(Bg + (size_t)(lk)     * bstride + lm);
        float4 b1 = *(const float4*)(Bg + (size_t)(lk + 8) * bstride + lm);
        *(float4*)&Bs[0][lk][lm]     = b0;
        *(float4*)&Bs[0][lk + 8][lm] = b1;
    }
    __syncthreads();

    int cur = 0;
#pragma unroll 1
    for (int kc = 0; kc < 8; ++kc) {
        float4 nv0, nv1, nb0, nb1;
        const bool more = (kc + 1) < 8;
        if (more) {
            int k0 = (kc + 1) * 16;
            nv0 = *(const float4*)(Ag + (size_t)am * R_ + k0 + ak);
            nv1 = *(const float4*)(Ag + (size_t)(am + 64) * R_ + k0 + ak);
            nb0 = *(const float4*)(Bg + (size_t)(k0 + lk)     * bstride + lm);
            nb1 = *(const float4*)(Bg + (size_t)(k0 + lk + 8) * bstride + lm);
        }
#pragma unroll
        for (int k = 0; k < 16; ++k) {
            float4 a0 = *(const float4*)&As[cur][k][ty * 4];
            float4 a1 = *(const float4*)&As[cur][k][64 + ty * 4];
            ulonglong2 b0 = *(const ulonglong2*)&Bs[cur][k][tx * 4];
            ulonglong2 b1 = *(const ulonglong2*)&Bs[cur][k][64 + tx * 4];
            unsigned long long ap[8];
            ap[0] = pack_dup(a0.x); ap[1] = pack_dup(a0.y);
            ap[2] = pack_dup(a0.z); ap[3] = pack_dup(a0.w);
            ap[4] = pack_dup(a1.x); ap[5] = pack_dup(a1.y);
            ap[6] = pack_dup(a1.z); ap[7] = pack_dup(a1.w);
#pragma unroll
            for (int i = 0; i < 8; ++i) {
                ffma2(acc[i][0], ap[i], b0.x);
                ffma2(acc[i][1], ap[i], b0.y);
                ffma2(acc[i][2], ap[i], b1.x);
                ffma2(acc[i][3], ap[i], b1.y);
            }
        }
        if (more) {
            int nxt = cur ^ 1;
            As[nxt][ak + 0][am] = nv0.x; As[nxt][ak + 1][am] = nv0.y;
            As[nxt][ak + 2][am] = nv0.z; As[nxt][ak + 3][am] = nv0.w;
            As[nxt][ak + 0][am + 64] = nv1.x; As[nxt][ak + 1][am + 64] = nv1.y;
            As[nxt][ak + 2][am + 64] = nv1.z; As[nxt][ak + 3][am + 64] = nv1.w;
            *(float4*)&Bs[nxt][lk][lm]     = nb0;
            *(float4*)&Bs[nxt][lk + 8][lm] = nb1;
            __syncthreads();
            cur = nxt;
        }
    }

    // store out[b][f][p][q], q < 126  (rows are 126 floats -> only 8B aligned)
#pragma unroll
    for (int i = 0; i < 8; ++i) {
        int fl = (i < 4) ? (ty * 4 + i) : (64 + ty * 4 + (i - 4));
        float* row = out + (((size_t)(b * F_ + m0 + fl)) * HP + p) * WP;
        float2 c0 = unpack2(acc[i][0]), c1 = unpack2(acc[i][1]);
        float2 c2 = unpack2(acc[i][2]), c3 = unpack2(acc[i][3]);
        const int q0 = tx * 4;        // 0..60, always valid
        *(float2*)(row + q0)     = c0;
        *(float2*)(row + q0 + 2) = c1;
        const int q1 = 64 + tx * 4;   // 64..124
        *(float2*)(row + q1) = c2;                     // q1,q1+1 <= 125 always
        if (q1 + 2 < WP) *(float2*)(row + q1 + 2) = c3; // skip q=126,127
    }
}

extern "C" void kernel_launch(void* const* d_in, const int* in_sizes, int n_in,
                              void* d_out, int out_size) {
    const float* x  = (const float*)d_in[0];
    const float* f0 = (const float*)d_in[1];
    const float* f1 = (const float*)d_in[2];
    const float* f2 = (const float*)d_in[3];
    const float* f3 = (const float*)d_in[4];
    float* out = (float*)d_out;

    // K1: per (h-row, batch) GEMM tiles
    k1_channel_mix<<<dim3(H_, B_), 256>>>(x, f3);
    // K2: depthwise 3x3 separable, 4 q-outputs per thread
    k2_depthwise<<<dim3(32, R_, B_), 128>>>(f1, f2);
    // K3: per (p-row, m-tile, batch) GEMM tiles
    k3_output_gemm<<<dim3(HP, F_ / 128, B_), 256>>>(f0, out);
}